// round 2
// baseline (speedup 1.0000x reference)
#include <cuda_runtime.h>
#include <math_constants.h>

#define PH 7
#define PW 7
#define C_ 256
#define H_ 50
#define W_ 50
#define R_ 256
#define WPB 8   // warps per block

// One warp per (roi, channel). Stage 1: coalesced row loads -> per-ph column
// maxes in registers. Stage 2: smem reduce across columns into pw bins.
__global__ __launch_bounds__(WPB * 32)
void roi_pool_fused(const float* __restrict__ feat,
                    const int* __restrict__ rois_raw,
                    float* __restrict__ out) {
    __shared__ float s_col[WPB][PH][64];

    const int warp = threadIdx.x >> 5;
    const int lane = threadIdx.x & 31;
    const int wg   = blockIdx.x * WPB + warp;
    const int r    = wg >> 8;    // / C_
    const int c    = wg & 255;   // % C_

    // dtype sniff: rois are int64 iff all odd 32-bit words of the first 40 are
    // zero (values < 800 so int64 high halves are 0; int32 layout puts sorted
    // random coords there, which cannot all be zero).
    int sniff = 0;
    if (lane < 20) sniff = rois_raw[2 * lane + 1];
    const bool is64 = !__any_sync(0xffffffffu, sniff != 0);

    // Load this roi's 5 words (lanes 0..4), broadcast via shuffle.
    int w0 = 0;
    if (lane < 5) w0 = is64 ? rois_raw[(r * 5 + lane) * 2] : rois_raw[r * 5 + lane];
    const int b  = __shfl_sync(0xffffffffu, w0, 0);
    const int x1 = __shfl_sync(0xffffffffu, w0, 1) >> 4;  // floor(x/16), x>=0
    const int y1 = __shfl_sync(0xffffffffu, w0, 2) >> 4;
    const int x2 = __shfl_sync(0xffffffffu, w0, 3) >> 4;
    const int y2 = __shfl_sync(0xffffffffu, w0, 4) >> 4;
    const int h = y2 - y1 + 1;
    const int w = x2 - x1 + 1;

    // Lanes 0..6 hold bin boundaries for ph=lane / pw=lane.
    int sh_l = 0, eh_l = 0, sw_l = 0, ew_l = 0;
    if (lane < PH) {
        sh_l = y1 + (lane * h) / PH;
        eh_l = y1 + ((lane + 1) * h + PH - 1) / PH;
        sw_l = x1 + (lane * w) / PW;
        ew_l = x1 + ((lane + 1) * w + PW - 1) / PW;
    }

    const float* __restrict__ base =
        feat + (size_t)(b * C_ + c) * (H_ * W_) + x1;
    const bool pa = lane < w;          // column slot 0 valid
    const bool pb = (lane + 32) < w;   // column slot 1 valid

    // ---- Stage 1: per-ph column maxes, coalesced row loads ----
#pragma unroll
    for (int ph = 0; ph < PH; ++ph) {
        const int sh = __shfl_sync(0xffffffffu, sh_l, ph);
        const int eh = __shfl_sync(0xffffffffu, eh_l, ph);
        float m0 = -CUDART_INF_F, m1 = -CUDART_INF_F;
        const float* p = base + sh * W_;
        for (int y = sh; y < eh; ++y, p += W_) {
            if (pa) m0 = fmaxf(m0, __ldg(p + lane));
            if (pb) m1 = fmaxf(m1, __ldg(p + lane + 32));
        }
        s_col[warp][ph][lane]      = m0;
        s_col[warp][ph][lane + 32] = m1;
    }
    __syncwarp();

    // ---- Stage 2: reduce columns into pw bins, write out ----
    float* __restrict__ o_base = out + (size_t)wg * (PH * PW);
#pragma unroll
    for (int o = lane; o < PH * PW; o += 32) {
        const int ph = o / PW;
        const int pw = o - ph * PW;
        const int sw = __shfl_sync(0xffffffffu, sw_l, pw);
        const int ew = __shfl_sync(0xffffffffu, ew_l, pw);
        float m = -CUDART_INF_F;
        const float* sc = &s_col[warp][ph][0];
        for (int x = sw - x1; x < ew - x1; ++x)
            m = fmaxf(m, sc[x]);
        o_base[o] = m;
    }
}

extern "C" void kernel_launch(void* const* d_in, const int* in_sizes, int n_in,
                              void* d_out, int out_size) {
    const float* feat = (const float*)d_in[0];
    const int*   rois = (const int*)d_in[1];
    float* out = (float*)d_out;

    const int total_warps = R_ * C_;         // 65536
    const int blocks = total_warps / WPB;    // 8192
    roi_pool_fused<<<blocks, WPB * 32>>>(feat, rois, out);
}

// round 3
// speedup vs baseline: 1.2369x; 1.2369x over previous
#include <cuda_runtime.h>
#include <math_constants.h>

#define PH 7
#define PW 7
#define B_ 4
#define C_ 256
#define H_ 50
#define W_ 50
#define HW_ (H_ * W_)
#define R_ 256

// NHWC scratch: g_featT[b][y*W+x][c]
__device__ float g_featT[B_ * HW_ * C_];

// ---- Kernel 1: tiled transpose (B,C,HW) -> (B,HW,C) ----
// Block 32x8, each block moves a 32(C) x 32(HW) tile.
__global__ __launch_bounds__(256)
void transpose_kernel(const float* __restrict__ feat) {
    __shared__ float tile[32][33];
    const int b   = blockIdx.z;
    const int c0  = blockIdx.y * 32;
    const int hw0 = blockIdx.x * 32;
    const int tx = threadIdx.x, ty = threadIdx.y;

    const float* src = feat + (size_t)b * C_ * HW_;
#pragma unroll
    for (int k = 0; k < 4; ++k) {
        int c  = c0 + ty + k * 8;
        int hw = hw0 + tx;
        if (hw < HW_)
            tile[ty + k * 8][tx] = src[(size_t)c * HW_ + hw];
    }
    __syncthreads();

    float* dst = g_featT + (size_t)b * HW_ * C_;
#pragma unroll
    for (int k = 0; k < 4; ++k) {
        int hw = hw0 + ty + k * 8;
        int c  = c0 + tx;
        if (hw < HW_)
            dst[(size_t)hw * C_ + c] = tile[tx][ty + k * 8];
    }
}

// ---- Kernel 2: ROI max pool on NHWC ----
// Grid = R_ * PH blocks; 256 threads = channels. Thread c computes the 7
// pw-bin maxes of its channel over this block's ph row-band. Every feature
// load is warp-coalesced (256 contiguous channel floats per (y,x)).
__global__ __launch_bounds__(256)
void roi_pool_nhwc(const int* __restrict__ rois_raw,
                   float* __restrict__ out) {
    __shared__ float s_out[C_ * PW];   // flat: s_out[c*7 + pw]

    const int bid = blockIdx.x;
    const int r   = bid / PH;
    const int ph  = bid - r * PH;
    const int c   = threadIdx.x;

    // dtype sniff (int64 iff all odd words of first 40 are zero; values < 800).
    int acc = 0;
#pragma unroll
    for (int i = 1; i < 40; i += 2) acc |= __ldg(rois_raw + i);
    const bool is64 = (acc == 0);

    int v[5];
#pragma unroll
    for (int i = 0; i < 5; ++i)
        v[i] = is64 ? __ldg(rois_raw + (r * 5 + i) * 2)
                    : __ldg(rois_raw + r * 5 + i);

    const int b  = v[0];
    const int x1 = v[1] >> 4;   // floor(x/16), x >= 0
    const int y1 = v[2] >> 4;
    const int x2 = v[3] >> 4;
    const int y2 = v[4] >> 4;
    const int h = y2 - y1 + 1;
    const int w = x2 - x1 + 1;

    const int sh = y1 + (ph * h) / PH;
    const int eh = y1 + ((ph + 1) * h + PH - 1) / PH;

    const float* __restrict__ base = g_featT + ((size_t)b * HW_) * C_ + c;

#pragma unroll
    for (int pw = 0; pw < PW; ++pw) {
        const int sw = x1 + (pw * w) / PW;
        const int ew = x1 + ((pw + 1) * w + PW - 1) / PW;
        float m = -CUDART_INF_F;
        for (int y = sh; y < eh; ++y) {
            const float* rp = base + (size_t)(y * W_ + sw) * C_;
            for (int x = sw; x < ew; ++x, rp += C_)
                m = fmaxf(m, __ldg(rp));
        }
        s_out[c * PW + pw] = m;
    }
    __syncthreads();

    // Stage out: block's 1792 values -> out[r][c][ph][pw].
    float* __restrict__ o_base = out + (size_t)r * (C_ * PH * PW) + ph * PW;
#pragma unroll
    for (int k = 0; k < PW; ++k) {
        int g  = c + k * C_;        // 0..1791, linear smem read
        int cc = g / PW;
        int pw = g - cc * PW;
        o_base[cc * (PH * PW) + pw] = s_out[g];
    }
}

extern "C" void kernel_launch(void* const* d_in, const int* in_sizes, int n_in,
                              void* d_out, int out_size) {
    const float* feat = (const float*)d_in[0];
    const int*   rois = (const int*)d_in[1];
    float* out = (float*)d_out;

    dim3 tgrid((HW_ + 31) / 32, C_ / 32, B_);   // 79 x 8 x 4
    dim3 tblk(32, 8);
    transpose_kernel<<<tgrid, tblk>>>(feat);

    roi_pool_nhwc<<<R_ * PH, C_>>>(rois, out);
}

// round 7
// speedup vs baseline: 1.5310x; 1.2378x over previous
#include <cuda_runtime.h>
#include <math_constants.h>

#define PH 7
#define PW 7
#define B_ 4
#define C_ 256
#define H_ 50
#define W_ 50
#define HW_ (H_ * W_)
#define R_ 256
#define OUT_PER_R (C_ * PH * PW)     // 12544
#define CQ 64                        // channels per block (quarter)
#define OUT_PER_BLK (CQ * PH * PW)   // 3136

// NHWC scratch: g_featT[b][y*W+x][c]
__device__ float g_featT[B_ * HW_ * C_];

// ---- Kernel 1: tiled transpose (B,C,HW) -> (B,HW,C) ----
__global__ __launch_bounds__(256)
void transpose_kernel(const float* __restrict__ feat) {
    __shared__ float tile[32][33];
    const int b   = blockIdx.z;
    const int c0  = blockIdx.y * 32;
    const int hw0 = blockIdx.x * 32;
    const int tx = threadIdx.x, ty = threadIdx.y;

    const float* src = feat + (size_t)b * C_ * HW_;
#pragma unroll
    for (int k = 0; k < 4; ++k) {
        int c  = c0 + ty + k * 8;
        int hw = hw0 + tx;
        if (hw < HW_)
            tile[ty + k * 8][tx] = src[(size_t)c * HW_ + hw];
    }
    __syncthreads();

    float* dst = g_featT + (size_t)b * HW_ * C_;
#pragma unroll
    for (int k = 0; k < 4; ++k) {
        int hw = hw0 + ty + k * 8;
        int c  = c0 + tx;
        if (hw < HW_)
            dst[(size_t)hw * C_ + c] = tile[tx][ty + k * 8];
    }
}

// ---- Kernel 2: one block per (ROI, channel-quarter) ----
// 256 threads = 16 c4-groups (4 channels each) x 16 bin-groups.
// Bin-group g handles (ph,pw) bins {g, g+16, g+32, g+48} < 49.
__global__ __launch_bounds__(256)
void roi_pool_nhwc(const int* __restrict__ rois_raw,
                   float* __restrict__ out) {
    __shared__ float s_out[OUT_PER_BLK];   // staged in final out layout
    __shared__ int s_roi[5];               // b, x1, y1, h, w

    const int r   = blockIdx.x;
    const int q   = blockIdx.y;            // channel quarter 0..3
    const int tid = threadIdx.x;
    const int g   = tid >> 4;              // bin group 0..15 (warp-spans-2)
    const int c4l = tid & 15;              // local float4 channel group 0..15

    if (tid == 0) {
        // dtype sniff: rois are int64 iff all odd words of the first 40 are
        // zero (coords < 800 so int64 high halves are 0; the int32 layout
        // puts nonzero sorted coords in those slots).
        int acc = 0;
#pragma unroll
        for (int i = 1; i < 40; i += 2) acc |= __ldg(rois_raw + i);
        const bool is64 = (acc == 0);

        int v[5];
#pragma unroll
        for (int i = 0; i < 5; ++i)
            v[i] = is64 ? __ldg(rois_raw + (r * 5 + i) * 2)
                        : __ldg(rois_raw + r * 5 + i);

        const int x1 = v[1] >> 4;   // floor(x/16), x >= 0
        const int y1 = v[2] >> 4;
        const int x2 = v[3] >> 4;
        const int y2 = v[4] >> 4;
        s_roi[0] = v[0];            // b
        s_roi[1] = x1;
        s_roi[2] = y1;
        s_roi[3] = y2 - y1 + 1;     // h
        s_roi[4] = x2 - x1 + 1;     // w
    }
    __syncthreads();

    const int b  = s_roi[0];
    const int x1 = s_roi[1];
    const int y1 = s_roi[2];
    const int h  = s_roi[3];
    const int w  = s_roi[4];

    const float4* __restrict__ base =
        (const float4*)(g_featT + (size_t)b * HW_ * C_)
        + (q * 16 + c4l);

#pragma unroll
    for (int bin = g; bin < PH * PW; bin += 16) {
        const int ph = bin / PW;            // const divide -> IMAD-hi
        const int pw = bin - ph * PW;
        const int sh = y1 + (ph * h) / PH;
        const int eh = y1 + ((ph + 1) * h + PH - 1) / PH;
        const int sw = x1 + (pw * w) / PW;
        const int ew = x1 + ((pw + 1) * w + PW - 1) / PW;

        float4 m = make_float4(-CUDART_INF_F, -CUDART_INF_F,
                               -CUDART_INF_F, -CUDART_INF_F);
        for (int y = sh; y < eh; ++y) {
            const float4* p = base + (y * W_ + sw) * (C_ / 4);
            for (int x = sw; x < ew; ++x, p += C_ / 4) {
                const float4 t = __ldg(p);
                m.x = fmaxf(m.x, t.x);
                m.y = fmaxf(m.y, t.y);
                m.z = fmaxf(m.z, t.z);
                m.w = fmaxf(m.w, t.w);
            }
        }
        // stage in final out layout: s_out[cl*49 + bin], cl = local channel
        const int cb = c4l * 4 * (PH * PW) + bin;
        s_out[cb]               = m.x;
        s_out[cb + PH * PW]     = m.y;
        s_out[cb + 2 * PH * PW] = m.z;
        s_out[cb + 3 * PH * PW] = m.w;
    }
    __syncthreads();

    // Fully coalesced writeback of this block's contiguous 3136-float range:
    // out[r][q*64 .. q*64+63][*][*]
    float4* __restrict__ o4 =
        (float4*)(out + (size_t)r * OUT_PER_R + q * OUT_PER_BLK);
    const float4* __restrict__ s4 = (const float4*)s_out;
#pragma unroll
    for (int k = 0; k < 4; ++k) {
        const int i = tid + k * 256;
        if (i < OUT_PER_BLK / 4)            // 784
            o4[i] = s4[i];
    }
}

extern "C" void kernel_launch(void* const* d_in, const int* in_sizes, int n_in,
                              void* d_out, int out_size) {
    const float* feat = (const float*)d_in[0];
    const int*   rois = (const int*)d_in[1];
    float* out = (float*)d_out;

    dim3 tgrid((HW_ + 31) / 32, C_ / 32, B_);
    dim3 tblk(32, 8);
    transpose_kernel<<<tgrid, tblk>>>(feat);

    dim3 pgrid(R_, 4);
    roi_pool_nhwc<<<pgrid, 256>>>(rois, out);
}

// round 9
// speedup vs baseline: 1.7443x; 1.1393x over previous
#include <cuda_runtime.h>
#include <math_constants.h>

#define PH 7
#define PW 7
#define B_ 4
#define C_ 256
#define C4_ (C_ / 4)
#define H_ 50
#define W_ 50
#define HW_ (H_ * W_)
#define R_ 256
#define OUT_PER_R (C_ * PH * PW)     // 12544
#define OUT_PER_BLK (64 * PH * PW)   // 3136 (channel quarter)

// NHWC scratch: g_featT[b][y*W+x][c]
__device__ float g_featT[B_ * HW_ * C_];
// Horizontal-pool intermediate: g_hmax[r][yi][pw][c], yi = y - y1 (0..49)
__device__ float g_hmax[R_ * 50 * PW * C_];   // 91.75 MB

__device__ __forceinline__ float4 fmax4(float4 a, float4 b) {
    return make_float4(fmaxf(a.x, b.x), fmaxf(a.y, b.y),
                       fmaxf(a.z, b.z), fmaxf(a.w, b.w));
}

// Decode ROI r (handles int64/int32 rois) into s5 = {b, x1, y1, h, w}.
__device__ __forceinline__ void decode_roi(const int* __restrict__ rois_raw,
                                           int r, int* s5) {
    // int64 iff all odd words of the first 40 are zero (coords < 800 so the
    // int64 high halves are 0; the int32 layout puts nonzero coords there).
    int acc = 0;
#pragma unroll
    for (int i = 1; i < 40; i += 2) acc |= __ldg(rois_raw + i);
    const bool is64 = (acc == 0);
    int v[5];
#pragma unroll
    for (int i = 0; i < 5; ++i)
        v[i] = is64 ? __ldg(rois_raw + (r * 5 + i) * 2)
                    : __ldg(rois_raw + r * 5 + i);
    const int x1 = v[1] >> 4;   // floor(x/16), x >= 0
    const int y1 = v[2] >> 4;
    const int x2 = v[3] >> 4;
    const int y2 = v[4] >> 4;
    s5[0] = v[0];               // b
    s5[1] = x1;
    s5[2] = y1;
    s5[3] = y2 - y1 + 1;        // h
    s5[4] = x2 - x1 + 1;        // w
}

// ---- Kernel 1: tiled transpose (B,C,HW) -> (B,HW,C) ----
__global__ __launch_bounds__(256)
void transpose_kernel(const float* __restrict__ feat) {
    __shared__ float tile[32][33];
    const int b   = blockIdx.z;
    const int c0  = blockIdx.y * 32;
    const int hw0 = blockIdx.x * 32;
    const int tx = threadIdx.x, ty = threadIdx.y;

    const float* src = feat + (size_t)b * C_ * HW_;
#pragma unroll
    for (int k = 0; k < 4; ++k) {
        int c  = c0 + ty + k * 8;
        int hw = hw0 + tx;
        if (hw < HW_)
            tile[ty + k * 8][tx] = src[(size_t)c * HW_ + hw];
    }
    __syncthreads();

    float* dst = g_featT + (size_t)b * HW_ * C_;
#pragma unroll
    for (int k = 0; k < 4; ++k) {
        int hw = hw0 + ty + k * 8;
        int c  = c0 + tx;
        if (hw < HW_)
            dst[(size_t)hw * C_ + c] = tile[tx][ty + k * 8];
    }
}

// ---- Kernel 2: horizontal pool ----
// Block (r, yi): 64 threads = float4 channel groups. Each thread walks the
// row span once (chunked 8-deep load batches) and merges into 7 pw bins.
// Bin bounds: sw(pw)=floor(pw*w/7), ew(pw)=ceil((pw+1)*w/7); consecutive bins
// overlap by at most the single element floor(pw*w/7). When w < 7, several
// bins close on the same element -> the while loop closes them all.
__global__ __launch_bounds__(64)
void hpool_kernel(const int* __restrict__ rois_raw) {
    __shared__ int s_roi[5];
    const int r  = blockIdx.x;
    const int yi = blockIdx.y;
    const int c4 = threadIdx.x;

    if (c4 == 0) decode_roi(rois_raw, r, s_roi);
    __syncthreads();

    const int b  = s_roi[0];
    const int x1 = s_roi[1];
    const int y1 = s_roi[2];
    const int h  = s_roi[3];
    const int w  = s_roi[4];
    if (yi >= h) return;

    const int y = y1 + yi;
    const float4* __restrict__ p =
        (const float4*)g_featT + ((size_t)b * HW_ + y * W_ + x1) * C4_ + c4;
    float* __restrict__ outp =
        g_hmax + ((size_t)(r * 50 + yi) * PW) * C_ + c4 * 4;

    const float4 NEG4 = make_float4(-CUDART_INF_F, -CUDART_INF_F,
                                    -CUDART_INF_F, -CUDART_INF_F);
    float4 m = NEG4;
    int pw   = 0;
    int last = (w + 6) / 7 - 1;   // ew(0)-1, x relative to x1

    for (int x0 = 0; x0 < w; x0 += 8) {
        float4 buf[8];
#pragma unroll
        for (int i = 0; i < 8; ++i) {
            int xx = x0 + i;
            if (xx > w - 1) xx = w - 1;     // clamp (in-bounds duplicate)
            buf[i] = __ldg(p + xx * C4_);
        }
#pragma unroll
        for (int i = 0; i < 8; ++i) {
            const int x = x0 + i;
            if (x < w) {                    // block-uniform
                const float4 t = buf[i];
                m = fmax4(m, t);
                while (pw < PW && x == last) {   // close all bins ending here
                    *(float4*)(outp + pw * C_) = m;
                    ++pw;
                    const int swn = (pw * w) / PW;  // next bin start
                    m = (swn == x) ? t : NEG4;      // <=1-elem overlap re-seed
                    last = ((pw + 1) * w + PW - 1) / PW - 1;
                }
            }
        }
    }
}

// ---- Kernel 3: vertical pool + coalesced writeback ----
// Block (r, q): 256 threads = 16 bin-groups x 16 local c4 groups over a
// 64-channel quarter. Bin-group g handles bins {g, g+16, g+32, g+48} < 49.
__global__ __launch_bounds__(256)
void vpool_kernel(const int* __restrict__ rois_raw,
                  float* __restrict__ out) {
    __shared__ float s_out[OUT_PER_BLK];
    __shared__ int s_roi[5];

    const int r   = blockIdx.x;
    const int q   = blockIdx.y;
    const int tid = threadIdx.x;
    const int g   = tid >> 4;
    const int c4l = tid & 15;

    if (tid == 0) decode_roi(rois_raw, r, s_roi);
    __syncthreads();
    const int h = s_roi[3];

    const float4 NEG4 = make_float4(-CUDART_INF_F, -CUDART_INF_F,
                                    -CUDART_INF_F, -CUDART_INF_F);

#pragma unroll
    for (int bin = g; bin < PH * PW; bin += 16) {
        const int ph  = bin / PW;
        const int pw  = bin - ph * PW;
        const int shi = (ph * h) / PH;
        const int ehi = ((ph + 1) * h + PH - 1) / PH;
        const int n   = ehi - shi;     // >= 1 always (h >= 1)

        const float4* __restrict__ p =
            (const float4*)g_hmax
            + ((size_t)(r * 50 + shi) * PW + pw) * C4_ + q * 16 + c4l;
        const int step = PW * C4_;

        float4 m = NEG4;
        for (int i0 = 0; i0 < n; i0 += 4) {
            float4 buf[4];
#pragma unroll
            for (int j = 0; j < 4; ++j) {
                int ii = i0 + j;
                if (ii > n - 1) ii = n - 1;   // clamp (duplicate ok for max)
                buf[j] = __ldg(p + ii * step);
            }
#pragma unroll
            for (int j = 0; j < 4; ++j)
                if (i0 + j < n) m = fmax4(m, buf[j]);
        }

        const int cb = c4l * 4 * (PH * PW) + bin;
        s_out[cb]               = m.x;
        s_out[cb + PH * PW]     = m.y;
        s_out[cb + 2 * PH * PW] = m.z;
        s_out[cb + 3 * PH * PW] = m.w;
    }
    __syncthreads();

    // Coalesced writeback of this block's contiguous 3136-float range.
    float4* __restrict__ o4 =
        (float4*)(out + (size_t)r * OUT_PER_R + q * OUT_PER_BLK);
    const float4* __restrict__ s4 = (const float4*)s_out;
#pragma unroll
    for (int k = 0; k < 4; ++k) {
        const int i = tid + k * 256;
        if (i < OUT_PER_BLK / 4)            // 784
            o4[i] = s4[i];
    }
}

extern "C" void kernel_launch(void* const* d_in, const int* in_sizes, int n_in,
                              void* d_out, int out_size) {
    const float* feat = (const float*)d_in[0];
    const int*   rois = (const int*)d_in[1];
    float* out = (float*)d_out;

    dim3 tgrid((HW_ + 31) / 32, C_ / 32, B_);
    dim3 tblk(32, 8);
    transpose_kernel<<<tgrid, tblk>>>(feat);

    dim3 hgrid(R_, 50);
    hpool_kernel<<<hgrid, 64>>>(rois);

    dim3 vgrid(R_, 4);
    vpool_kernel<<<vgrid, 256>>>(rois, out);
}